// round 14
// baseline (speedup 1.0000x reference)
#include <cuda_runtime.h>
#include <math.h>

// DistinctionLoss: two-kernel, single-wave, max-MLP version.
// features [8,4096,256] f32, scores [8,4096,1] f32 -> scalar f32.
//
// mean(gram) = sum_b ||s_b||^2 / (B*N^2), s_b = sum_n unit(features[b,n,:]).
// Kernel 1: per-row 1/norm + s_b accumulation.
// Kernel 2: per-row dot vs s_b -> smem; 256-wide BCE tail; last block (ticket)
//           finalizes ||s_b||^2, combines, writes out, resets state.
// 128 blocks x 256 threads (one wave), 32 rows/warp in 4 batches of 8:
// 16 LDG.128 hoisted per batch -> ~8KB in flight per warp.

#define BB 8
#define NN 4096
#define DD 256
#define NBLK 128
#define NTHREADS 256
#define NWARPS (NTHREADS / 32)                   // 8
#define ROWS_PER_BLOCK ((BB * NN) / NBLK)        // 256
#define ROWS_PER_WARP  (ROWS_PER_BLOCK / NWARPS) // 32
#define RBATCH 8

// Persistent scratch; zero-initialized at module load, self-reset each launch.
__device__ float  g_rnorm[BB * NN];
__device__ float  g_s[BB * DD];
__device__ double g_bce;
__device__ unsigned int g_ticket;

// ---------------- Kernel 1: row norms + s_b accumulation ----------------
__global__ void __launch_bounds__(NTHREADS) pass1_kernel(const float* __restrict__ feat) {
    __shared__ float s_acc[DD];
    int tid  = threadIdx.x;
    int wid  = tid >> 5;
    int lane = tid & 31;
    s_acc[tid] = 0.0f;
    __syncthreads();

    int rowBase = blockIdx.x * ROWS_PER_BLOCK;   // 256 | 4096 -> single batch
    int b       = rowBase >> 12;
    int row0    = rowBase + wid * ROWS_PER_WARP;

    float4 acc0 = make_float4(0.f, 0.f, 0.f, 0.f);
    float4 acc1 = make_float4(0.f, 0.f, 0.f, 0.f);

    for (int rb = 0; rb < ROWS_PER_WARP; rb += RBATCH) {
        float4 a0[RBATCH], a1[RBATCH];
        #pragma unroll
        for (int r = 0; r < RBATCH; r++) {        // 16 independent LDG.128
            const float4* p = (const float4*)(feat + (size_t)(row0 + rb + r) * DD);
            a0[r] = p[lane];
            a1[r] = p[lane + 32];
        }
        float ss[RBATCH];
        #pragma unroll
        for (int r = 0; r < RBATCH; r++)
            ss[r] = a0[r].x*a0[r].x + a0[r].y*a0[r].y + a0[r].z*a0[r].z + a0[r].w*a0[r].w
                  + a1[r].x*a1[r].x + a1[r].y*a1[r].y + a1[r].z*a1[r].z + a1[r].w*a1[r].w;
        #pragma unroll
        for (int o = 16; o > 0; o >>= 1) {        // 8 interleaved butterflies
            #pragma unroll
            for (int r = 0; r < RBATCH; r++)
                ss[r] += __shfl_xor_sync(0xffffffffu, ss[r], o);
        }
        #pragma unroll
        for (int r = 0; r < RBATCH; r++) {
            float rn = rsqrtf(fmaxf(ss[r], 1e-24f));
            if (lane == 0) g_rnorm[row0 + rb + r] = rn;
            acc0.x += a0[r].x * rn; acc0.y += a0[r].y * rn;
            acc0.z += a0[r].z * rn; acc0.w += a0[r].w * rn;
            acc1.x += a1[r].x * rn; acc1.y += a1[r].y * rn;
            acc1.z += a1[r].z * rn; acc1.w += a1[r].w * rn;
        }
    }

    int d0 = lane * 4;
    atomicAdd(&s_acc[d0 + 0],       acc0.x);
    atomicAdd(&s_acc[d0 + 1],       acc0.y);
    atomicAdd(&s_acc[d0 + 2],       acc0.z);
    atomicAdd(&s_acc[d0 + 3],       acc0.w);
    atomicAdd(&s_acc[128 + d0 + 0], acc1.x);
    atomicAdd(&s_acc[128 + d0 + 1], acc1.y);
    atomicAdd(&s_acc[128 + d0 + 2], acc1.z);
    atomicAdd(&s_acc[128 + d0 + 3], acc1.w);
    __syncthreads();

    atomicAdd(&g_s[b * DD + tid], s_acc[tid]);
}

// -------- Kernel 2: streaming dots -> parallel BCE tail -> finalize --------
__global__ void __launch_bounds__(NTHREADS) pass2_kernel(const float* __restrict__ feat,
                                                         const float* __restrict__ scores,
                                                         float* __restrict__ out) {
    __shared__ float s_fs[ROWS_PER_BLOCK];       // raw dot per row (256)
    __shared__ float s_red[NWARPS];
    int tid  = threadIdx.x;
    int wid  = tid >> 5;
    int lane = tid & 31;

    int rowBase = blockIdx.x * ROWS_PER_BLOCK;
    int b       = rowBase >> 12;
    int row0    = rowBase + wid * ROWS_PER_WARP;

    // Lane-mapped s_b slices (atomics from pass1 landed in L2).
    const float4* gs4 = (const float4*)(g_s + b * DD);
    float4 s0 = __ldcg(&gs4[lane]);
    float4 s1 = __ldcg(&gs4[lane + 32]);

    for (int rb = 0; rb < ROWS_PER_WARP; rb += RBATCH) {
        float4 a0[RBATCH], a1[RBATCH];
        #pragma unroll
        for (int r = 0; r < RBATCH; r++) {        // 16 independent LDG.128
            const float4* p = (const float4*)(feat + (size_t)(row0 + rb + r) * DD);
            a0[r] = p[lane];
            a1[r] = p[lane + 32];
        }
        float dt[RBATCH];
        #pragma unroll
        for (int r = 0; r < RBATCH; r++)
            dt[r] = a0[r].x*s0.x + a0[r].y*s0.y + a0[r].z*s0.z + a0[r].w*s0.w
                  + a1[r].x*s1.x + a1[r].y*s1.y + a1[r].z*s1.z + a1[r].w*s1.w;
        #pragma unroll
        for (int o = 16; o > 0; o >>= 1) {        // 8 interleaved butterflies
            #pragma unroll
            for (int r = 0; r < RBATCH; r++)
                dt[r] += __shfl_xor_sync(0xffffffffu, dt[r], o);
        }
        if (lane == 0) {
            #pragma unroll
            for (int r = 0; r < RBATCH; r++)
                s_fs[wid * ROWS_PER_WARP + rb + r] = dt[r];
        }
    }
    __syncthreads();

    // ---- 256-wide BCE tail: one thread per row ----
    int row   = rowBase + tid;
    float fs  = s_fs[tid] * g_rnorm[row];
    float sim = (fs - 1.0f) * (1.0f / (float)(NN - 1));
    float t   = 1.0f - fmaxf(sim, 0.0f);
    float sc  = scores[row];
    float ls  = fmaxf(__logf(sc),        -100.0f);
    float l1  = fmaxf(__logf(1.0f - sc), -100.0f);
    float local = -(t * ls + (1.0f - t) * l1);

    #pragma unroll
    for (int o = 16; o > 0; o >>= 1)
        local += __shfl_xor_sync(0xffffffffu, local, o);
    if (lane == 0) s_red[wid] = local;
    __syncthreads();

    __shared__ unsigned int s_am_last;
    if (tid == 0) {
        float sum = 0.0f;
        #pragma unroll
        for (int i = 0; i < NWARPS; i++) sum += s_red[i];
        atomicAdd(&g_bce, (double)sum);
        __threadfence();                               // publish before ticket
        s_am_last = (atomicAdd(&g_ticket, 1u) == NBLK - 1);
    }
    __syncthreads();
    if (!s_am_last) return;

    // ---- Last block: all NBLK BCE atomics are visible. Finalize. ----
    __threadfence();                                   // acquire side
    float ss = 0.0f;
    #pragma unroll
    for (int i = 0; i < (BB * DD) / NTHREADS; i++) {
        float v = __ldcg(&g_s[tid + i * NTHREADS]);
        ss += v * v;
    }
    #pragma unroll
    for (int o = 16; o > 0; o >>= 1)
        ss += __shfl_xor_sync(0xffffffffu, ss, o);
    if (lane == 0) s_red[wid] = ss;
    __syncthreads();
    if (wid == 0) {
        float t2 = (lane < NWARPS) ? s_red[lane] : 0.0f;
        #pragma unroll
        for (int o = 4; o > 0; o >>= 1)
            t2 += __shfl_xor_sync(0xffffffffu, t2, o);
        if (lane == 0) {
            double bce       = atomicAdd(&g_bce, 0.0) / (double)(BB * NN);
            double mean_gram = (double)t2 /
                               ((double)BB * (double)NN * (double)NN);
            out[0] = (float)(bce + (1.0 - mean_gram));
            g_bce    = 0.0;                            // reset for next launch
            g_ticket = 0u;
        }
    }
    __syncthreads();                                   // all reads of g_s done
    #pragma unroll
    for (int i = 0; i < (BB * DD) / NTHREADS; i++)
        g_s[tid + i * NTHREADS] = 0.0f;                // reset for next launch
}

extern "C" void kernel_launch(void* const* d_in, const int* in_sizes, int n_in,
                              void* d_out, int out_size) {
    const float* feat   = (const float*)d_in[0];
    const float* scores = (const float*)d_in[1];
    float* out = (float*)d_out;

    pass1_kernel<<<NBLK, NTHREADS>>>(feat);
    pass2_kernel<<<NBLK, NTHREADS>>>(feat, scores, out);
}

// round 15
// speedup vs baseline: 1.3345x; 1.3345x over previous
#include <cuda_runtime.h>
#include <cuda_bf16.h>
#include <math.h>

// DistinctionLoss: two-kernel version with bf16 unit-row scratch.
// features [8,4096,256] f32, scores [8,4096,1] f32 -> scalar f32.
//
// mean(gram) = sum_b ||s_b||^2 / (B*N^2), s_b = sum_n unit(features[b,n,:]).
// Kernel 1: per-row 1/norm + s_b accumulation + write unit row as bf16 (16MB).
// Kernel 2: read bf16 unit rows (half traffic, no rnorm), dot vs s_b -> BCE;
//           last block (ticket) finalizes ||s_b||^2, combines, resets state.
// 512 blocks x 256 threads (best-measured shape, R12 = 17.3us).

#define BB 8
#define NN 4096
#define DD 256
#define NBLK 512
#define NTHREADS 256
#define NWARPS (NTHREADS / 32)                   // 8
#define ROWS_PER_BLOCK ((BB * NN) / NBLK)        // 64
#define ROWS_PER_WARP  (ROWS_PER_BLOCK / NWARPS) // 8

// Persistent scratch; zero-initialized at module load, self-reset each launch.
__device__ uint2  g_unit[BB * NN * 64];          // bf16 unit rows: 64 x 8B per row
__device__ float  g_s[BB * DD];
__device__ double g_bce;
__device__ unsigned int g_ticket;

// ---------------- Kernel 1: norms + s_b accum + bf16 unit-row store ----------
__global__ void __launch_bounds__(NTHREADS) pass1_kernel(const float* __restrict__ feat) {
    __shared__ float s_acc[DD];
    int tid  = threadIdx.x;
    int wid  = tid >> 5;
    int lane = tid & 31;
    s_acc[tid] = 0.0f;
    __syncthreads();

    int rowBase = blockIdx.x * ROWS_PER_BLOCK;   // 64 | 4096 -> single batch
    int b       = rowBase >> 12;
    int row0    = rowBase + wid * ROWS_PER_WARP;

    float4 acc0 = make_float4(0.f, 0.f, 0.f, 0.f);
    float4 acc1 = make_float4(0.f, 0.f, 0.f, 0.f);

    #pragma unroll
    for (int r = 0; r < ROWS_PER_WARP; r++) {
        int row = row0 + r;
        const float4* p = (const float4*)(feat + (size_t)row * DD);
        float4 v0 = p[lane];                     // elements 4*lane .. +3
        float4 v1 = p[lane + 32];                // elements 128+4*lane .. +3
        float ss = v0.x*v0.x + v0.y*v0.y + v0.z*v0.z + v0.w*v0.w
                 + v1.x*v1.x + v1.y*v1.y + v1.z*v1.z + v1.w*v1.w;
        #pragma unroll
        for (int o = 16; o > 0; o >>= 1)
            ss += __shfl_xor_sync(0xffffffffu, ss, o);
        float rn = rsqrtf(fmaxf(ss, 1e-24f));

        float4 u0, u1;
        u0.x = v0.x * rn; u0.y = v0.y * rn; u0.z = v0.z * rn; u0.w = v0.w * rn;
        u1.x = v1.x * rn; u1.y = v1.y * rn; u1.z = v1.z * rn; u1.w = v1.w * rn;
        acc0.x += u0.x; acc0.y += u0.y; acc0.z += u0.z; acc0.w += u0.w;
        acc1.x += u1.x; acc1.y += u1.y; acc1.z += u1.z; acc1.w += u1.w;

        // pack + store bf16 unit row (layout mirrors the float4 lane mapping)
        __nv_bfloat162 pA = __floats2bfloat162_rn(u0.x, u0.y);
        __nv_bfloat162 pB = __floats2bfloat162_rn(u0.z, u0.w);
        __nv_bfloat162 pC = __floats2bfloat162_rn(u1.x, u1.y);
        __nv_bfloat162 pD = __floats2bfloat162_rn(u1.z, u1.w);
        uint2 wA, wB;
        wA.x = *reinterpret_cast<unsigned int*>(&pA);
        wA.y = *reinterpret_cast<unsigned int*>(&pB);
        wB.x = *reinterpret_cast<unsigned int*>(&pC);
        wB.y = *reinterpret_cast<unsigned int*>(&pD);
        g_unit[(size_t)row * 64 + lane]      = wA;
        g_unit[(size_t)row * 64 + 32 + lane] = wB;
    }

    int d0 = lane * 4;
    atomicAdd(&s_acc[d0 + 0],       acc0.x);
    atomicAdd(&s_acc[d0 + 1],       acc0.y);
    atomicAdd(&s_acc[d0 + 2],       acc0.z);
    atomicAdd(&s_acc[d0 + 3],       acc0.w);
    atomicAdd(&s_acc[128 + d0 + 0], acc1.x);
    atomicAdd(&s_acc[128 + d0 + 1], acc1.y);
    atomicAdd(&s_acc[128 + d0 + 2], acc1.z);
    atomicAdd(&s_acc[128 + d0 + 3], acc1.w);
    __syncthreads();

    atomicAdd(&g_s[b * DD + tid], s_acc[tid]);
}

// ------ Kernel 2: bf16 unit-row dots -> parallel BCE tail -> finalize ------
__global__ void __launch_bounds__(NTHREADS) pass2_kernel(const float* __restrict__ scores,
                                                         float* __restrict__ out) {
    __shared__ float s_fs[ROWS_PER_BLOCK];       // fs per row (64)
    __shared__ float s_red[NWARPS];
    int tid  = threadIdx.x;
    int wid  = tid >> 5;
    int lane = tid & 31;

    int rowBase = blockIdx.x * ROWS_PER_BLOCK;
    int b       = rowBase >> 12;
    int row0    = rowBase + wid * ROWS_PER_WARP;

    // Lane-mapped s_b slices (elements 4*lane.. and 128+4*lane..).
    const float4* gs4 = (const float4*)(g_s + b * DD);
    float4 s0 = __ldcg(&gs4[lane]);
    float4 s1 = __ldcg(&gs4[lane + 32]);

    // Hoist all 16 LDG.64 (8 rows x 2) -> max MLP, ~32 data regs.
    uint2 uLo[ROWS_PER_WARP], uHi[ROWS_PER_WARP];
    #pragma unroll
    for (int r = 0; r < ROWS_PER_WARP; r++) {
        uLo[r] = g_unit[(size_t)(row0 + r) * 64 + lane];
        uHi[r] = g_unit[(size_t)(row0 + r) * 64 + 32 + lane];
    }

    float dt[ROWS_PER_WARP];
    #pragma unroll
    for (int r = 0; r < ROWS_PER_WARP; r++) {
        float2 f0 = __bfloat1622float2(*reinterpret_cast<__nv_bfloat162*>(&uLo[r].x));
        float2 f1 = __bfloat1622float2(*reinterpret_cast<__nv_bfloat162*>(&uLo[r].y));
        float2 f2 = __bfloat1622float2(*reinterpret_cast<__nv_bfloat162*>(&uHi[r].x));
        float2 f3 = __bfloat1622float2(*reinterpret_cast<__nv_bfloat162*>(&uHi[r].y));
        dt[r] = f0.x*s0.x + f0.y*s0.y + f1.x*s0.z + f1.y*s0.w
              + f2.x*s1.x + f2.y*s1.y + f3.x*s1.z + f3.y*s1.w;
    }
    #pragma unroll
    for (int o = 16; o > 0; o >>= 1) {           // 8 interleaved butterflies
        #pragma unroll
        for (int r = 0; r < ROWS_PER_WARP; r++)
            dt[r] += __shfl_xor_sync(0xffffffffu, dt[r], o);
    }
    if (lane == 0) {
        #pragma unroll
        for (int r = 0; r < ROWS_PER_WARP; r++)
            s_fs[wid * ROWS_PER_WARP + r] = dt[r];   // fs = unit-row . s_b
    }
    __syncthreads();

    // ---- 64-wide BCE tail: one thread per row ----
    float local = 0.0f;
    if (tid < ROWS_PER_BLOCK) {
        int row   = rowBase + tid;
        float fs  = s_fs[tid];
        float sim = (fs - 1.0f) * (1.0f / (float)(NN - 1));
        float t   = 1.0f - fmaxf(sim, 0.0f);
        float sc  = scores[row];
        float ls  = fmaxf(__logf(sc),        -100.0f);
        float l1  = fmaxf(__logf(1.0f - sc), -100.0f);
        local = -(t * ls + (1.0f - t) * l1);
    }
    #pragma unroll
    for (int o = 16; o > 0; o >>= 1)
        local += __shfl_xor_sync(0xffffffffu, local, o);
    if (lane == 0) s_red[wid] = local;
    __syncthreads();

    __shared__ unsigned int s_am_last;
    if (tid == 0) {
        atomicAdd(&g_bce, (double)(s_red[0] + s_red[1]));
        __threadfence();                               // publish before ticket
        s_am_last = (atomicAdd(&g_ticket, 1u) == NBLK - 1);
    }
    __syncthreads();
    if (!s_am_last) return;

    // ---- Last block: all NBLK BCE atomics are visible. Finalize. ----
    __threadfence();                                   // acquire side
    float ss = 0.0f;
    #pragma unroll
    for (int i = 0; i < (BB * DD) / NTHREADS; i++) {
        float v = __ldcg(&g_s[tid + i * NTHREADS]);
        ss += v * v;
    }
    #pragma unroll
    for (int o = 16; o > 0; o >>= 1)
        ss += __shfl_xor_sync(0xffffffffu, ss, o);
    if (lane == 0) s_red[wid] = ss;
    __syncthreads();
    if (wid == 0) {
        float t2 = (lane < NWARPS) ? s_red[lane] : 0.0f;
        #pragma unroll
        for (int o = 4; o > 0; o >>= 1)
            t2 += __shfl_xor_sync(0xffffffffu, t2, o);
        if (lane == 0) {
            double bce       = atomicAdd(&g_bce, 0.0) / (double)(BB * NN);
            double mean_gram = (double)t2 /
                               ((double)BB * (double)NN * (double)NN);
            out[0] = (float)(bce + (1.0 - mean_gram));
            g_bce    = 0.0;                            // reset for next launch
            g_ticket = 0u;
        }
    }
    __syncthreads();                                   // all reads of g_s done
    #pragma unroll
    for (int i = 0; i < (BB * DD) / NTHREADS; i++)
        g_s[tid + i * NTHREADS] = 0.0f;                // reset for next launch
}

extern "C" void kernel_launch(void* const* d_in, const int* in_sizes, int n_in,
                              void* d_out, int out_size) {
    const float* feat   = (const float*)d_in[0];
    const float* scores = (const float*)d_in[1];
    float* out = (float*)d_out;

    pass1_kernel<<<NBLK, NTHREADS>>>(feat);
    pass2_kernel<<<NBLK, NTHREADS>>>(scores, out);
}